// round 1
// baseline (speedup 1.0000x reference)
#include <cuda_runtime.h>
#include <math.h>

// ---------------- static problem shape ----------------
#define BATCH 32
#define IMGH  56
#define IMGW  56
#define CCH   192
#define LLEN  (IMGH*IMGW)        // 3136
#define NHEAD 6
#define HDIM  32
#define WSZ   7
#define SHIFT_ 3
#define LW    49                 // 7*7
#define NWIN  64                 // 8*8 windows per image
#define NWTOT (BATCH*NWIN)       // 2048
#define MTOK  (BATCH*LLEN)       // 100352

// ---------------- scratch (device globals; no allocation allowed) ----------------
__device__ float g_xw  [(size_t)MTOK*CCH];     // LN1 + roll + window partition
__device__ float g_qkv [(size_t)MTOK*3*CCH];   // qkv in window layout
__device__ float g_attn[(size_t)MTOK*CCH];     // attention output (window layout)
__device__ float g_proj[(size_t)MTOK*CCH];     // proj output (window layout)
__device__ float g_xres[(size_t)MTOK*CCH];     // x + attn branch (original layout)
__device__ float g_ln2 [(size_t)MTOK*CCH];     // LN2 output
__device__ float g_h1  [(size_t)MTOK*4*CCH];   // fc1+gelu output

__device__ __forceinline__ float gelu_exact(float x) {
    return 0.5f * x * (1.0f + erff(x * 0.70710678118654752f));
}

// ---------------- LayerNorm (192 ch), optional roll+window remap ----------------
// one block per token, 192 threads
template<bool WINDOW_MAP>
__global__ void ln_kernel(const float* __restrict__ in,
                          const float* __restrict__ gamma,
                          const float* __restrict__ beta,
                          float* __restrict__ out)
{
    const int m = blockIdx.x;          // token in original layout
    const int c = threadIdx.x;         // 0..191
    const float v = in[(size_t)m*CCH + c];

    // block reduction over 6 warps
    float s = v, s2 = v*v;
    #pragma unroll
    for (int off = 16; off > 0; off >>= 1) {
        s  += __shfl_down_sync(0xffffffff, s,  off);
        s2 += __shfl_down_sync(0xffffffff, s2, off);
    }
    __shared__ float red[12];
    const int lane = c & 31, wid = c >> 5;
    if (lane == 0) { red[wid] = s; red[6+wid] = s2; }
    __syncthreads();
    __shared__ float stats[2];
    if (c == 0) {
        float ts = 0.f, ts2 = 0.f;
        #pragma unroll
        for (int i = 0; i < 6; ++i) { ts += red[i]; ts2 += red[6+i]; }
        const float mean = ts * (1.0f/CCH);
        const float var  = ts2 * (1.0f/CCH) - mean*mean;
        stats[0] = mean;
        stats[1] = rsqrtf(var + 1e-5f);
    }
    __syncthreads();
    const float y = (v - stats[0]) * stats[1] * gamma[c] + beta[c];

    if (WINDOW_MAP) {
        const int b = m / LLEN, l = m % LLEN;
        const int h = l / IMGW, w = l % IMGW;
        int hp = h - SHIFT_; if (hp < 0) hp += IMGH;   // rolled coords
        int wp = w - SHIFT_; if (wp < 0) wp += IMGW;
        const int widx  = b*NWIN + (hp/WSZ)*8 + (wp/WSZ);
        const int local = (hp%WSZ)*WSZ + (wp%WSZ);
        out[(size_t)(widx*LW + local)*CCH + c] = y;
    } else {
        out[(size_t)m*CCH + c] = y;
    }
}

// ---------------- SGEMM: OUT[M,N] = A[M,K] @ W[N,K]^T (+bias)(+gelu)(+res) ----------------
// BM=128, BN=64, BK=16, 256 threads, 8x4 per thread
template<int ACT, bool HAS_BIAS, bool HAS_RES>
__global__ void __launch_bounds__(256)
gemm_kernel(const float* __restrict__ A, const float* __restrict__ W,
            const float* __restrict__ bias, const float* __restrict__ res,
            float* __restrict__ out, int M, int N, int K)
{
    const int tid = threadIdx.x;
    const int tx = tid & 15;           // n-tile 0..15 (x4)
    const int ty = tid >> 4;           // m-tile 0..15 (x8)
    const int n0 = blockIdx.x * 64;
    const int m0 = blockIdx.y * 128;

    __shared__ float As[16][128];
    __shared__ float Bs[16][64];

    float acc[8][4];
    #pragma unroll
    for (int i = 0; i < 8; ++i)
        #pragma unroll
        for (int j = 0; j < 4; ++j) acc[i][j] = 0.f;

    for (int k0 = 0; k0 < K; k0 += 16) {
        // A tile: 128x16 = 512 float4, 2 per thread
        #pragma unroll
        for (int r = 0; r < 2; ++r) {
            const int q   = tid + r*256;
            const int row = q >> 2;
            const int c4  = (q & 3) << 2;
            const float4 v = *reinterpret_cast<const float4*>(
                &A[(size_t)(m0+row)*K + k0 + c4]);
            As[c4+0][row] = v.x; As[c4+1][row] = v.y;
            As[c4+2][row] = v.z; As[c4+3][row] = v.w;
        }
        // W tile: 64x16 = 256 float4, 1 per thread
        {
            const int row = tid >> 2;
            const int c4  = (tid & 3) << 2;
            const float4 v = *reinterpret_cast<const float4*>(
                &W[(size_t)(n0+row)*K + k0 + c4]);
            Bs[c4+0][row] = v.x; Bs[c4+1][row] = v.y;
            Bs[c4+2][row] = v.z; Bs[c4+3][row] = v.w;
        }
        __syncthreads();
        #pragma unroll
        for (int kk = 0; kk < 16; ++kk) {
            float a[8], b[4];
            #pragma unroll
            for (int i = 0; i < 8; ++i) a[i] = As[kk][ty*8 + i];
            #pragma unroll
            for (int j = 0; j < 4; ++j) b[j] = Bs[kk][tx*4 + j];
            #pragma unroll
            for (int i = 0; i < 8; ++i)
                #pragma unroll
                for (int j = 0; j < 4; ++j)
                    acc[i][j] += a[i] * b[j];
        }
        __syncthreads();
    }

    #pragma unroll
    for (int i = 0; i < 8; ++i) {
        const int m = m0 + ty*8 + i;
        #pragma unroll
        for (int j = 0; j < 4; ++j) {
            const int n = n0 + tx*4 + j;
            float v = acc[i][j];
            if (HAS_BIAS) v += bias[n];
            if (ACT == 1) v = gelu_exact(v);
            if (HAS_RES)  v += res[(size_t)m*N + n];
            out[(size_t)m*N + n] = v;
        }
    }
}

// ---------------- fused attention per (window, head) ----------------
__device__ __forceinline__ int regid(int p) { return (p < 49) ? 0 : ((p < 53) ? 1 : 2); }

__global__ void __launch_bounds__(128)
attn_kernel(const float* __restrict__ rel_bias)
{
    const int h = blockIdx.x;          // head
    const int w = blockIdx.y;          // global window index
    const int tid = threadIdx.x;

    __shared__ float sQ[LW*33];
    __shared__ float sK[LW*33];
    __shared__ float sV[LW*32];
    __shared__ float sS[LW*LW];

    // load q/k/v slices for this head
    for (int t = tid; t < LW*HDIM; t += 128) {
        const int i = t >> 5, d = t & 31;
        const size_t base = (size_t)(w*LW + i) * (3*CCH);
        sQ[i*33 + d] = g_qkv[base + h*HDIM + d];
        sK[i*33 + d] = g_qkv[base + CCH + h*HDIM + d];
        sV[i*32 + d] = g_qkv[base + 2*CCH + h*HDIM + d];
    }
    __syncthreads();

    // scores + bias + shift mask (computed on the fly)
    const int wl  = w & (NWIN-1);
    const int wh_ = wl >> 3, ww_ = wl & 7;
    for (int t = tid; t < LW*LW; t += 128) {
        const int i = t / LW, j = t % LW;
        const int ih = i / WSZ, iw = i % WSZ;
        const int jh = j / WSZ, jw = j % WSZ;
        const int idi = regid(wh_*WSZ + ih)*3 + regid(ww_*WSZ + iw);
        const int idj = regid(wh_*WSZ + jh)*3 + regid(ww_*WSZ + jw);
        float sval;
        if (idi != idj) {
            sval = -100.0f;
        } else {
            float acc = 0.f;
            #pragma unroll
            for (int d = 0; d < HDIM; ++d)
                acc += sQ[i*33 + d] * sK[j*33 + d];
            // faithful quirk: scale by C**0.5
            const int bidx = ((ih - jh + 6)*13 + (iw - jw + 6));
            sval = acc * 13.856406460551018f + rel_bias[bidx*NHEAD + h];
        }
        sS[i*LW + j] = sval;
    }
    __syncthreads();

    // row softmax (49 rows, one thread each)
    if (tid < LW) {
        float mx = -1e30f;
        #pragma unroll
        for (int j = 0; j < LW; ++j) mx = fmaxf(mx, sS[tid*LW + j]);
        float sum = 0.f;
        #pragma unroll
        for (int j = 0; j < LW; ++j) {
            const float e = expf(sS[tid*LW + j] - mx);
            sS[tid*LW + j] = e;
            sum += e;
        }
        const float inv = 1.0f / sum;
        #pragma unroll
        for (int j = 0; j < LW; ++j) sS[tid*LW + j] *= inv;
    }
    __syncthreads();

    // out = P @ V  -> window layout, channel = h*32+d
    for (int t = tid; t < LW*HDIM; t += 128) {
        const int i = t >> 5, d = t & 31;
        float acc = 0.f;
        #pragma unroll
        for (int j = 0; j < LW; ++j)
            acc += sS[i*LW + j] * sV[j*32 + d];
        g_attn[(size_t)(w*LW + i)*CCH + h*HDIM + d] = acc;
    }
}

// ---------------- window-reverse + unroll + residual ----------------
__global__ void scatter_res_kernel(const float* __restrict__ x)
{
    const long total = (long)MTOK * CCH;
    for (long idx = (long)blockIdx.x*blockDim.x + threadIdx.x;
         idx < total; idx += (long)gridDim.x*blockDim.x) {
        const int m = (int)(idx / CCH);
        const int c = (int)(idx % CCH);
        const int b = m / LLEN, l = m % LLEN;
        const int h = l / IMGW, w = l % IMGW;
        int hp = h - SHIFT_; if (hp < 0) hp += IMGH;
        int wp = w - SHIFT_; if (wp < 0) wp += IMGW;
        const int widx  = b*NWIN + (hp/WSZ)*8 + (wp/WSZ);
        const int local = (hp%WSZ)*WSZ + (wp%WSZ);
        g_xres[idx] = x[idx] + g_proj[(size_t)(widx*LW + local)*CCH + c];
    }
}

// ---------------- launch ----------------
extern "C" void kernel_launch(void* const* d_in, const int* in_sizes, int n_in,
                              void* d_out, int out_size)
{
    // collect non-scalar inputs in declaration order (skips H, W ints if present)
    const void* arr[20];
    int na = 0;
    for (int i = 0; i < n_in && na < 20; ++i)
        if (in_sizes[i] != 1) arr[na++] = d_in[i];
    // order: x, attn_mask, relative_coords, norm1_w, norm1_b, qkv_w, rel_bias,
    //        proj_w, proj_b, norm2_w, norm2_b, fc1_w, fc1_b, fc2_w, fc2_b
    const float* x     = (const float*)arr[0];
    const float* n1w   = (const float*)arr[3];
    const float* n1b   = (const float*)arr[4];
    const float* qkvw  = (const float*)arr[5];
    const float* relb  = (const float*)arr[6];
    const float* projw = (const float*)arr[7];
    const float* projb = (const float*)arr[8];
    const float* n2w   = (const float*)arr[9];
    const float* n2b   = (const float*)arr[10];
    const float* fc1w  = (const float*)arr[11];
    const float* fc1b  = (const float*)arr[12];
    const float* fc2w  = (const float*)arr[13];
    const float* fc2b  = (const float*)arr[14];
    float* out = (float*)d_out;

    float* p_xw;   cudaGetSymbolAddress((void**)&p_xw,   g_xw);
    float* p_qkv;  cudaGetSymbolAddress((void**)&p_qkv,  g_qkv);
    float* p_attn; cudaGetSymbolAddress((void**)&p_attn, g_attn);
    float* p_proj; cudaGetSymbolAddress((void**)&p_proj, g_proj);
    float* p_xres; cudaGetSymbolAddress((void**)&p_xres, g_xres);
    float* p_ln2;  cudaGetSymbolAddress((void**)&p_ln2,  g_ln2);
    float* p_h1;   cudaGetSymbolAddress((void**)&p_h1,   g_h1);

    // 1) LN1 + roll + window partition
    ln_kernel<true><<<MTOK, CCH>>>(x, n1w, n1b, p_xw);

    // 2) QKV GEMM: (100352,192) x (576,192)^T
    gemm_kernel<0, false, false><<<dim3(576/64, MTOK/128), 256>>>(
        p_xw, qkvw, nullptr, nullptr, p_qkv, MTOK, 3*CCH, CCH);

    // 3) fused windowed attention
    attn_kernel<<<dim3(NHEAD, NWTOT), 128>>>(relb);

    // 4) proj GEMM (+bias)
    gemm_kernel<0, true, false><<<dim3(192/64, MTOK/128), 256>>>(
        p_attn, projw, projb, nullptr, p_proj, MTOK, CCH, CCH);

    // 5) window reverse + roll back + residual
    scatter_res_kernel<<<4096, 256>>>(x);

    // 6) LN2
    ln_kernel<false><<<MTOK, CCH>>>(p_xres, n2w, n2b, p_ln2);

    // 7) fc1 GEMM + bias + gelu
    gemm_kernel<1, true, false><<<dim3(768/64, MTOK/128), 256>>>(
        p_ln2, fc1w, fc1b, nullptr, p_h1, MTOK, 4*CCH, CCH);

    // 8) fc2 GEMM + bias + gelu (faithful quirk) + residual -> d_out
    gemm_kernel<1, true, true><<<dim3(192/64, MTOK/128), 256>>>(
        p_h1, fc2w, fc2b, p_xres, out, MTOK, CCH, 4*CCH);

    (void)out_size;
}

// round 2
// speedup vs baseline: 1.9385x; 1.9385x over previous
#include <cuda_runtime.h>
#include <math.h>
#include <stdint.h>

// ---------------- static problem shape ----------------
#define BATCH 32
#define IMGH  56
#define IMGW  56
#define CCH   192
#define LLEN  (IMGH*IMGW)        // 3136
#define NHEAD 6
#define HDIM  32
#define WSZ   7
#define SHIFT_ 3
#define LW    49                 // 7*7
#define NWIN  64                 // 8*8 windows per image
#define NWTOT (BATCH*NWIN)       // 2048
#define MTOK  (BATCH*LLEN)       // 100352

// ---------------- scratch (device globals; no allocation allowed) ----------------
__device__ float g_xw  [(size_t)MTOK*CCH];     // LN1 + roll + window partition
__device__ float g_qkv [(size_t)MTOK*3*CCH];   // qkv in window layout
__device__ float g_attn[(size_t)MTOK*CCH];     // attention output (window layout)
__device__ float g_proj[(size_t)MTOK*CCH];     // proj output (window layout)
__device__ float g_xres[(size_t)MTOK*CCH];     // x + attn branch (original layout)
__device__ float g_ln2 [(size_t)MTOK*CCH];     // LN2 output
__device__ float g_h1  [(size_t)MTOK*4*CCH];   // fc1+gelu output

__device__ __forceinline__ float gelu_exact(float x) {
    return 0.5f * x * (1.0f + erff(x * 0.70710678118654752f));
}

__device__ __forceinline__ uint32_t f2tf32(float f) {
    uint32_t o;
    asm("cvt.rna.tf32.f32 %0, %1;" : "=r"(o) : "f"(f));
    return o;
}

__device__ __forceinline__ void mma_tf32(float c[4], const uint32_t a[4], const uint32_t b[2]) {
    asm volatile(
        "mma.sync.aligned.m16n8k8.row.col.f32.tf32.tf32.f32 "
        "{%0,%1,%2,%3}, {%4,%5,%6,%7}, {%8,%9}, {%0,%1,%2,%3};"
        : "+f"(c[0]), "+f"(c[1]), "+f"(c[2]), "+f"(c[3])
        : "r"(a[0]), "r"(a[1]), "r"(a[2]), "r"(a[3]), "r"(b[0]), "r"(b[1]));
}

// ---------------- LayerNorm (192 ch), optional roll+window remap ----------------
template<bool WINDOW_MAP>
__global__ void ln_kernel(const float* __restrict__ in,
                          const float* __restrict__ gamma,
                          const float* __restrict__ beta,
                          float* __restrict__ out)
{
    const int m = blockIdx.x;
    const int c = threadIdx.x;
    const float v = in[(size_t)m*CCH + c];

    float s = v, s2 = v*v;
    #pragma unroll
    for (int off = 16; off > 0; off >>= 1) {
        s  += __shfl_down_sync(0xffffffff, s,  off);
        s2 += __shfl_down_sync(0xffffffff, s2, off);
    }
    __shared__ float red[12];
    const int lane = c & 31, wid = c >> 5;
    if (lane == 0) { red[wid] = s; red[6+wid] = s2; }
    __syncthreads();
    __shared__ float stats[2];
    if (c == 0) {
        float ts = 0.f, ts2 = 0.f;
        #pragma unroll
        for (int i = 0; i < 6; ++i) { ts += red[i]; ts2 += red[6+i]; }
        const float mean = ts * (1.0f/CCH);
        const float var  = ts2 * (1.0f/CCH) - mean*mean;
        stats[0] = mean;
        stats[1] = rsqrtf(var + 1e-5f);
    }
    __syncthreads();
    const float y = (v - stats[0]) * stats[1] * gamma[c] + beta[c];

    if (WINDOW_MAP) {
        const int b = m / LLEN, l = m % LLEN;
        const int h = l / IMGW, w = l % IMGW;
        int hp = h - SHIFT_; if (hp < 0) hp += IMGH;
        int wp = w - SHIFT_; if (wp < 0) wp += IMGW;
        const int widx  = b*NWIN + (hp/WSZ)*8 + (wp/WSZ);
        const int local = (hp%WSZ)*WSZ + (wp%WSZ);
        out[(size_t)(widx*LW + local)*CCH + c] = y;
    } else {
        out[(size_t)m*CCH + c] = y;
    }
}

// ---------------- TF32 tensor-core GEMM: OUT[M,N] = A[M,K] @ W[N,K]^T ----------------
// BM=128, BN=64, BK=32; 256 threads = 8 warps (4 M x 2 N), warp tile 32x32.
// Smem layout [row][k], row stride 36 words (== 4 mod 32) => conflict-free
// float4 transposeless stores AND conflict-free MMA-fragment LDS reads.
#define GT_AS 36
template<int ACT, bool HAS_BIAS, bool HAS_RES>
__global__ void __launch_bounds__(256)
gemm_tc(const float* __restrict__ A, const float* __restrict__ W,
        const float* __restrict__ bias, const float* __restrict__ res,
        float* __restrict__ out, int M, int N, int K)
{
    const int tid  = threadIdx.x;
    const int lane = tid & 31;
    const int warp = tid >> 5;
    const int warpM = warp & 3;        // 0..3 -> 32-row slab
    const int warpN = warp >> 2;       // 0..1 -> 32-col slab
    const int m0 = blockIdx.y * 128;
    const int n0 = blockIdx.x * 64;

    __shared__ uint32_t As[128*GT_AS];
    __shared__ uint32_t Bs[64*GT_AS];

    float acc[2][4][4];
    #pragma unroll
    for (int i = 0; i < 2; ++i)
        #pragma unroll
        for (int j = 0; j < 4; ++j)
            #pragma unroll
            for (int q = 0; q < 4; ++q) acc[i][j][q] = 0.f;

    const int aRow[4] = { (tid+  0)>>3, (tid+256)>>3, (tid+512)>>3, (tid+768)>>3 };
    const int aK4     = (tid & 7) << 2;
    const int bRow[2] = { (tid+  0)>>3, (tid+256)>>3 };

    float4 ra[4], rb[2];
    // prefetch tile 0
    #pragma unroll
    for (int r = 0; r < 4; ++r)
        ra[r] = *reinterpret_cast<const float4*>(&A[(size_t)(m0 + aRow[r])*K + aK4]);
    #pragma unroll
    for (int r = 0; r < 2; ++r)
        rb[r] = *reinterpret_cast<const float4*>(&W[(size_t)(n0 + bRow[r])*K + aK4]);

    const int ntiles = K >> 5;
    for (int t = 0; t < ntiles; ++t) {
        // store current tile to smem (with tf32 conversion)
        #pragma unroll
        for (int r = 0; r < 4; ++r) {
            uint32_t* p = &As[aRow[r]*GT_AS + aK4];
            p[0] = f2tf32(ra[r].x); p[1] = f2tf32(ra[r].y);
            p[2] = f2tf32(ra[r].z); p[3] = f2tf32(ra[r].w);
        }
        #pragma unroll
        for (int r = 0; r < 2; ++r) {
            uint32_t* p = &Bs[bRow[r]*GT_AS + aK4];
            p[0] = f2tf32(rb[r].x); p[1] = f2tf32(rb[r].y);
            p[2] = f2tf32(rb[r].z); p[3] = f2tf32(rb[r].w);
        }
        __syncthreads();

        // prefetch next tile (LDG latency overlapped with MMA work)
        if (t + 1 < ntiles) {
            const int k0 = (t+1) << 5;
            #pragma unroll
            for (int r = 0; r < 4; ++r)
                ra[r] = *reinterpret_cast<const float4*>(&A[(size_t)(m0 + aRow[r])*K + k0 + aK4]);
            #pragma unroll
            for (int r = 0; r < 2; ++r)
                rb[r] = *reinterpret_cast<const float4*>(&W[(size_t)(n0 + bRow[r])*K + k0 + aK4]);
        }

        // 4 k-steps of 8
        #pragma unroll
        for (int kk = 0; kk < 4; ++kk) {
            const int kb = kk*8 + (lane & 3);
            uint32_t af[2][4], bf[4][2];
            #pragma unroll
            for (int mt = 0; mt < 2; ++mt) {
                const int rowb = warpM*32 + mt*16 + (lane >> 2);
                af[mt][0] = As[(rowb    )*GT_AS + kb    ];
                af[mt][1] = As[(rowb + 8)*GT_AS + kb    ];
                af[mt][2] = As[(rowb    )*GT_AS + kb + 4];
                af[mt][3] = As[(rowb + 8)*GT_AS + kb + 4];
            }
            #pragma unroll
            for (int nt = 0; nt < 4; ++nt) {
                const int nb = warpN*32 + nt*8 + (lane >> 2);
                bf[nt][0] = Bs[nb*GT_AS + kb    ];
                bf[nt][1] = Bs[nb*GT_AS + kb + 4];
            }
            #pragma unroll
            for (int mt = 0; mt < 2; ++mt)
                #pragma unroll
                for (int nt = 0; nt < 4; ++nt)
                    mma_tf32(acc[mt][nt], af[mt], bf[nt]);
        }
        __syncthreads();
    }

    // epilogue
    #pragma unroll
    for (int mt = 0; mt < 2; ++mt) {
        #pragma unroll
        for (int nt = 0; nt < 4; ++nt) {
            const int col = n0 + warpN*32 + nt*8 + ((lane & 3) << 1);
            const float b0 = HAS_BIAS ? bias[col]   : 0.f;
            const float b1 = HAS_BIAS ? bias[col+1] : 0.f;
            #pragma unroll
            for (int half = 0; half < 2; ++half) {
                const int row = m0 + warpM*32 + mt*16 + (lane >> 2) + half*8;
                float v0 = acc[mt][nt][half*2+0] + b0;
                float v1 = acc[mt][nt][half*2+1] + b1;
                if (ACT == 1) { v0 = gelu_exact(v0); v1 = gelu_exact(v1); }
                if (HAS_RES) {
                    const float2 r2 = *reinterpret_cast<const float2*>(&res[(size_t)row*N + col]);
                    v0 += r2.x; v1 += r2.y;
                }
                *reinterpret_cast<float2*>(&out[(size_t)row*N + col]) = make_float2(v0, v1);
            }
        }
    }
}

// ---------------- fused attention per (window, head) ----------------
__device__ __forceinline__ int regid(int p) { return (p < 49) ? 0 : ((p < 53) ? 1 : 2); }

__global__ void __launch_bounds__(128)
attn_kernel(const float* __restrict__ rel_bias)
{
    const int h = blockIdx.x;
    const int w = blockIdx.y;
    const int tid = threadIdx.x;

    __shared__ float sQ[LW*33];
    __shared__ float sK[LW*33];
    __shared__ float sV[LW*32];
    __shared__ float sS[LW*LW];

    for (int t = tid; t < LW*HDIM; t += 128) {
        const int i = t >> 5, d = t & 31;
        const size_t base = (size_t)(w*LW + i) * (3*CCH);
        sQ[i*33 + d] = g_qkv[base + h*HDIM + d];
        sK[i*33 + d] = g_qkv[base + CCH + h*HDIM + d];
        sV[i*32 + d] = g_qkv[base + 2*CCH + h*HDIM + d];
    }
    __syncthreads();

    const int wl  = w & (NWIN-1);
    const int wh_ = wl >> 3, ww_ = wl & 7;
    for (int t = tid; t < LW*LW; t += 128) {
        const int i = t / LW, j = t % LW;
        const int ih = i / WSZ, iw = i % WSZ;
        const int jh = j / WSZ, jw = j % WSZ;
        const int idi = regid(wh_*WSZ + ih)*3 + regid(ww_*WSZ + iw);
        const int idj = regid(wh_*WSZ + jh)*3 + regid(ww_*WSZ + jw);
        float sval;
        if (idi != idj) {
            sval = -100.0f;
        } else {
            float acc = 0.f;
            #pragma unroll
            for (int d = 0; d < HDIM; ++d)
                acc += sQ[i*33 + d] * sK[j*33 + d];
            const int bidx = ((ih - jh + 6)*13 + (iw - jw + 6));
            sval = acc * 13.856406460551018f + rel_bias[bidx*NHEAD + h];
        }
        sS[i*LW + j] = sval;
    }
    __syncthreads();

    if (tid < LW) {
        float mx = -1e30f;
        #pragma unroll
        for (int j = 0; j < LW; ++j) mx = fmaxf(mx, sS[tid*LW + j]);
        float sum = 0.f;
        #pragma unroll
        for (int j = 0; j < LW; ++j) {
            const float e = expf(sS[tid*LW + j] - mx);
            sS[tid*LW + j] = e;
            sum += e;
        }
        const float inv = 1.0f / sum;
        #pragma unroll
        for (int j = 0; j < LW; ++j) sS[tid*LW + j] *= inv;
    }
    __syncthreads();

    for (int t = tid; t < LW*HDIM; t += 128) {
        const int i = t >> 5, d = t & 31;
        float acc = 0.f;
        #pragma unroll
        for (int j = 0; j < LW; ++j)
            acc += sS[i*LW + j] * sV[j*32 + d];
        g_attn[(size_t)(w*LW + i)*CCH + h*HDIM + d] = acc;
    }
}

// ---------------- window-reverse + unroll + residual ----------------
__global__ void scatter_res_kernel(const float* __restrict__ x)
{
    const long total = (long)MTOK * CCH;
    for (long idx = (long)blockIdx.x*blockDim.x + threadIdx.x;
         idx < total; idx += (long)gridDim.x*blockDim.x) {
        const int m = (int)(idx / CCH);
        const int c = (int)(idx % CCH);
        const int b = m / LLEN, l = m % LLEN;
        const int h = l / IMGW, w = l % IMGW;
        int hp = h - SHIFT_; if (hp < 0) hp += IMGH;
        int wp = w - SHIFT_; if (wp < 0) wp += IMGW;
        const int widx  = b*NWIN + (hp/WSZ)*8 + (wp/WSZ);
        const int local = (hp%WSZ)*WSZ + (wp%WSZ);
        g_xres[idx] = x[idx] + g_proj[(size_t)(widx*LW + local)*CCH + c];
    }
}

// ---------------- launch ----------------
extern "C" void kernel_launch(void* const* d_in, const int* in_sizes, int n_in,
                              void* d_out, int out_size)
{
    const void* arr[20];
    int na = 0;
    for (int i = 0; i < n_in && na < 20; ++i)
        if (in_sizes[i] != 1) arr[na++] = d_in[i];
    const float* x     = (const float*)arr[0];
    const float* n1w   = (const float*)arr[3];
    const float* n1b   = (const float*)arr[4];
    const float* qkvw  = (const float*)arr[5];
    const float* relb  = (const float*)arr[6];
    const float* projw = (const float*)arr[7];
    const float* projb = (const float*)arr[8];
    const float* n2w   = (const float*)arr[9];
    const float* n2b   = (const float*)arr[10];
    const float* fc1w  = (const float*)arr[11];
    const float* fc1b  = (const float*)arr[12];
    const float* fc2w  = (const float*)arr[13];
    const float* fc2b  = (const float*)arr[14];
    float* out = (float*)d_out;

    float* p_xw;   cudaGetSymbolAddress((void**)&p_xw,   g_xw);
    float* p_qkv;  cudaGetSymbolAddress((void**)&p_qkv,  g_qkv);
    float* p_attn; cudaGetSymbolAddress((void**)&p_attn, g_attn);
    float* p_proj; cudaGetSymbolAddress((void**)&p_proj, g_proj);
    float* p_xres; cudaGetSymbolAddress((void**)&p_xres, g_xres);
    float* p_ln2;  cudaGetSymbolAddress((void**)&p_ln2,  g_ln2);
    float* p_h1;   cudaGetSymbolAddress((void**)&p_h1,   g_h1);

    // 1) LN1 + roll + window partition
    ln_kernel<true><<<MTOK, CCH>>>(x, n1w, n1b, p_xw);

    // 2) QKV GEMM: (100352,192) x (576,192)^T
    gemm_tc<0, false, false><<<dim3(576/64, MTOK/128), 256>>>(
        p_xw, qkvw, nullptr, nullptr, p_qkv, MTOK, 3*CCH, CCH);

    // 3) fused windowed attention
    attn_kernel<<<dim3(NHEAD, NWTOT), 128>>>(relb);

    // 4) proj GEMM (+bias)
    gemm_tc<0, true, false><<<dim3(192/64, MTOK/128), 256>>>(
        p_attn, projw, projb, nullptr, p_proj, MTOK, CCH, CCH);

    // 5) window reverse + roll back + residual
    scatter_res_kernel<<<4096, 256>>>(x);

    // 6) LN2
    ln_kernel<false><<<MTOK, CCH>>>(p_xres, n2w, n2b, p_ln2);

    // 7) fc1 GEMM + bias + gelu
    gemm_tc<1, true, false><<<dim3(768/64, MTOK/128), 256>>>(
        p_ln2, fc1w, fc1b, nullptr, p_h1, MTOK, 4*CCH, CCH);

    // 8) fc2 GEMM + bias + gelu (faithful quirk) + residual -> d_out
    gemm_tc<1, true, true><<<dim3(192/64, MTOK/128), 256>>>(
        p_h1, fc2w, fc2b, p_xres, out, MTOK, CCH, 4*CCH);

    (void)out_size;
}

// round 3
// speedup vs baseline: 2.2503x; 1.1608x over previous
#include <cuda_runtime.h>
#include <cuda_bf16.h>
#include <math.h>
#include <stdint.h>

// ---------------- static problem shape ----------------
#define BATCH 32
#define IMGH  56
#define IMGW  56
#define CCH   192
#define LLEN  (IMGH*IMGW)        // 3136
#define NHEAD 6
#define HDIM  32
#define WSZ   7
#define SHIFT_ 3
#define LW    49                 // 7*7
#define NWIN  64                 // 8*8 windows per image
#define NWTOT (BATCH*NWIN)       // 2048
#define MTOK  (BATCH*LLEN)       // 100352

// ---------------- scratch (device globals; no allocation allowed) ----------------
__device__ float g_xw  [(size_t)MTOK*CCH];
__device__ float g_qkv [(size_t)MTOK*3*CCH];
__device__ float g_attn[(size_t)MTOK*CCH];
__device__ float g_proj[(size_t)MTOK*CCH];
__device__ float g_xres[(size_t)MTOK*CCH];
__device__ float g_ln2 [(size_t)MTOK*CCH];
__device__ float g_h1  [(size_t)MTOK*4*CCH];

__device__ __forceinline__ float gelu_exact(float x) {
    return 0.5f * x * (1.0f + erff(x * 0.70710678118654752f));
}

// pack two fp32 -> bf16x2 (lo = first/even-k element in low 16 bits)
__device__ __forceinline__ uint32_t pack_bf16x2(float lo, float hi) {
    uint32_t o;
    asm("cvt.rn.bf16x2.f32 %0, %1, %2;" : "=r"(o) : "f"(hi), "f"(lo));
    return o;
}

__device__ __forceinline__ void mma_bf16(float c[4], const uint32_t a[4], const uint32_t b[2]) {
    asm volatile(
        "mma.sync.aligned.m16n8k16.row.col.f32.bf16.bf16.f32 "
        "{%0,%1,%2,%3}, {%4,%5,%6,%7}, {%8,%9}, {%0,%1,%2,%3};"
        : "+f"(c[0]), "+f"(c[1]), "+f"(c[2]), "+f"(c[3])
        : "r"(a[0]), "r"(a[1]), "r"(a[2]), "r"(a[3]), "r"(b[0]), "r"(b[1]));
}

// ---------------- LayerNorm (192 ch), optional roll+window remap ----------------
template<bool WINDOW_MAP>
__global__ void ln_kernel(const float* __restrict__ in,
                          const float* __restrict__ gamma,
                          const float* __restrict__ beta,
                          float* __restrict__ out)
{
    const int m = blockIdx.x;
    const int c = threadIdx.x;
    const float v = in[(size_t)m*CCH + c];

    float s = v, s2 = v*v;
    #pragma unroll
    for (int off = 16; off > 0; off >>= 1) {
        s  += __shfl_down_sync(0xffffffff, s,  off);
        s2 += __shfl_down_sync(0xffffffff, s2, off);
    }
    __shared__ float red[12];
    const int lane = c & 31, wid = c >> 5;
    if (lane == 0) { red[wid] = s; red[6+wid] = s2; }
    __syncthreads();
    __shared__ float stats[2];
    if (c == 0) {
        float ts = 0.f, ts2 = 0.f;
        #pragma unroll
        for (int i = 0; i < 6; ++i) { ts += red[i]; ts2 += red[6+i]; }
        const float mean = ts * (1.0f/CCH);
        const float var  = ts2 * (1.0f/CCH) - mean*mean;
        stats[0] = mean;
        stats[1] = rsqrtf(var + 1e-5f);
    }
    __syncthreads();
    const float y = (v - stats[0]) * stats[1] * gamma[c] + beta[c];

    if (WINDOW_MAP) {
        const int b = m / LLEN, l = m % LLEN;
        const int h = l / IMGW, w = l % IMGW;
        int hp = h - SHIFT_; if (hp < 0) hp += IMGH;
        int wp = w - SHIFT_; if (wp < 0) wp += IMGW;
        const int widx  = b*NWIN + (hp/WSZ)*8 + (wp/WSZ);
        const int local = (hp%WSZ)*WSZ + (wp%WSZ);
        out[(size_t)(widx*LW + local)*CCH + c] = y;
    } else {
        out[(size_t)m*CCH + c] = y;
    }
}

// ---------------- BF16 tensor-core GEMM: OUT[M,N] = A[M,K] @ W[N,K]^T ----------------
// BM=128, BN=64, BK=32; 256 threads = 8 warps (4 M x 2 N), warp tile 32x32.
// Smem word layout [row][kw], kw = k/2 packed bf16x2, row stride 20 words
// (16 data + 4 pad) => fragment LDS provably conflict-free.
// Double-buffered smem: one __syncthreads per k-tile; store of t+1 overlaps MMA of t.
#define RS 20                     // row stride in uint32 words
#define ABUF (128*RS)             // 2560 words per A stage
#define BBUF (64*RS)              // 1280 words per B stage
template<int ACT, bool HAS_BIAS, bool HAS_RES>
__global__ void __launch_bounds__(256)
gemm_tc(const float* __restrict__ A, const float* __restrict__ W,
        const float* __restrict__ bias, const float* __restrict__ res,
        float* __restrict__ out, int M, int N, int K)
{
    const int tid  = threadIdx.x;
    const int lane = tid & 31;
    const int warp = tid >> 5;
    const int warpM = warp & 3;
    const int warpN = warp >> 2;
    const int m0 = blockIdx.y * 128;
    const int n0 = blockIdx.x * 64;

    __shared__ uint32_t sA[2*ABUF];
    __shared__ uint32_t sB[2*BBUF];

    float acc[2][4][4];
    #pragma unroll
    for (int i = 0; i < 2; ++i)
        #pragma unroll
        for (int j = 0; j < 4; ++j)
            #pragma unroll
            for (int q = 0; q < 4; ++q) acc[i][j][q] = 0.f;

    // global load mapping: 32 floats/row per tile; float4 per thread slot
    const int aK4 = (tid & 7) << 2;          // float offset within 32
    const int kw0 = (tid & 7) << 1;          // word offset within 16
    const int aR0 = tid >> 3;                // rows 0..31 (+32 per rep)
    // per-warp LDS bases (compile-time offsets from these)
    const int laneR = lane >> 2;             // 0..7
    const int laneK = lane & 3;              // 0..3
    uint32_t* baseA = &sA[(warpM*32 + laneR)*RS + laneK];
    uint32_t* baseB = &sB[(warpN*32 + laneR)*RS + laneK];

    float4 ra[4], rb[2];
    #pragma unroll
    for (int r = 0; r < 4; ++r)
        ra[r] = *reinterpret_cast<const float4*>(&A[(size_t)(m0 + aR0 + r*32)*K + aK4]);
    #pragma unroll
    for (int r = 0; r < 2; ++r)
        rb[r] = *reinterpret_cast<const float4*>(&W[(size_t)(n0 + aR0 + r*32)*K + aK4]);

    // store tile 0 into stage 0
    #pragma unroll
    for (int r = 0; r < 4; ++r) {
        uint32_t* p = &sA[(aR0 + r*32)*RS + kw0];
        p[0] = pack_bf16x2(ra[r].x, ra[r].y);
        p[1] = pack_bf16x2(ra[r].z, ra[r].w);
    }
    #pragma unroll
    for (int r = 0; r < 2; ++r) {
        uint32_t* p = &sB[(aR0 + r*32)*RS + kw0];
        p[0] = pack_bf16x2(rb[r].x, rb[r].y);
        p[1] = pack_bf16x2(rb[r].z, rb[r].w);
    }

    const int ntiles = K >> 5;
    for (int t = 0; t < ntiles; ++t) {
        __syncthreads();
        const bool more = (t + 1 < ntiles);
        if (more) {
            const int k0 = (t+1) << 5;
            #pragma unroll
            for (int r = 0; r < 4; ++r)
                ra[r] = *reinterpret_cast<const float4*>(&A[(size_t)(m0 + aR0 + r*32)*K + k0 + aK4]);
            #pragma unroll
            for (int r = 0; r < 2; ++r)
                rb[r] = *reinterpret_cast<const float4*>(&W[(size_t)(n0 + aR0 + r*32)*K + k0 + aK4]);
        }

        const uint32_t* pA = baseA + (t & 1)*ABUF;
        const uint32_t* pB = baseB + (t & 1)*BBUF;
        // two k-steps of 16
        #pragma unroll
        for (int ks = 0; ks < 2; ++ks) {
            uint32_t af[2][4], bf[4][2];
            #pragma unroll
            for (int mt = 0; mt < 2; ++mt) {
                const uint32_t* q = pA + mt*(16*RS) + ks*8;
                af[mt][0] = q[0];
                af[mt][1] = q[8*RS];
                af[mt][2] = q[4];
                af[mt][3] = q[8*RS + 4];
            }
            #pragma unroll
            for (int nt = 0; nt < 4; ++nt) {
                const uint32_t* q = pB + nt*(8*RS) + ks*8;
                bf[nt][0] = q[0];
                bf[nt][1] = q[4];
            }
            #pragma unroll
            for (int mt = 0; mt < 2; ++mt)
                #pragma unroll
                for (int nt = 0; nt < 4; ++nt)
                    mma_bf16(acc[mt][nt], af[mt], bf[nt]);
        }

        if (more) {
            const int st = (t + 1) & 1;
            #pragma unroll
            for (int r = 0; r < 4; ++r) {
                uint32_t* p = &sA[st*ABUF + (aR0 + r*32)*RS + kw0];
                p[0] = pack_bf16x2(ra[r].x, ra[r].y);
                p[1] = pack_bf16x2(ra[r].z, ra[r].w);
            }
            #pragma unroll
            for (int r = 0; r < 2; ++r) {
                uint32_t* p = &sB[st*BBUF + (aR0 + r*32)*RS + kw0];
                p[0] = pack_bf16x2(rb[r].x, rb[r].y);
                p[1] = pack_bf16x2(rb[r].z, rb[r].w);
            }
        }
    }

    // epilogue (same c-fragment mapping as m16n8k8)
    #pragma unroll
    for (int mt = 0; mt < 2; ++mt) {
        #pragma unroll
        for (int nt = 0; nt < 4; ++nt) {
            const int col = n0 + warpN*32 + nt*8 + (laneK << 1);
            const float b0 = HAS_BIAS ? bias[col]   : 0.f;
            const float b1 = HAS_BIAS ? bias[col+1] : 0.f;
            #pragma unroll
            for (int half = 0; half < 2; ++half) {
                const int row = m0 + warpM*32 + mt*16 + laneR + half*8;
                float v0 = acc[mt][nt][half*2+0] + b0;
                float v1 = acc[mt][nt][half*2+1] + b1;
                if (ACT == 1) { v0 = gelu_exact(v0); v1 = gelu_exact(v1); }
                if (HAS_RES) {
                    const float2 r2 = *reinterpret_cast<const float2*>(&res[(size_t)row*N + col]);
                    v0 += r2.x; v1 += r2.y;
                }
                *reinterpret_cast<float2*>(&out[(size_t)row*N + col]) = make_float2(v0, v1);
            }
        }
    }
}

// ---------------- fused attention per (window, head) ----------------
__device__ __forceinline__ int regid(int p) { return (p < 49) ? 0 : ((p < 53) ? 1 : 2); }

__global__ void __launch_bounds__(128)
attn_kernel(const float* __restrict__ rel_bias)
{
    const int h = blockIdx.x;
    const int w = blockIdx.y;
    const int tid = threadIdx.x;

    __shared__ float sQ[LW*33];
    __shared__ float sK[LW*33];
    __shared__ float sV[LW*32];
    __shared__ float sS[LW*LW];

    for (int t = tid; t < LW*HDIM; t += 128) {
        const int i = t >> 5, d = t & 31;
        const size_t base = (size_t)(w*LW + i) * (3*CCH);
        sQ[i*33 + d] = g_qkv[base + h*HDIM + d];
        sK[i*33 + d] = g_qkv[base + CCH + h*HDIM + d];
        sV[i*32 + d] = g_qkv[base + 2*CCH + h*HDIM + d];
    }
    __syncthreads();

    const int wl  = w & (NWIN-1);
    const int wh_ = wl >> 3, ww_ = wl & 7;
    for (int t = tid; t < LW*LW; t += 128) {
        const int i = t / LW, j = t % LW;
        const int ih = i / WSZ, iw = i % WSZ;
        const int jh = j / WSZ, jw = j % WSZ;
        const int idi = regid(wh_*WSZ + ih)*3 + regid(ww_*WSZ + iw);
        const int idj = regid(wh_*WSZ + jh)*3 + regid(ww_*WSZ + jw);
        float sval;
        if (idi != idj) {
            sval = -100.0f;
        } else {
            float acc = 0.f;
            #pragma unroll
            for (int d = 0; d < HDIM; ++d)
                acc += sQ[i*33 + d] * sK[j*33 + d];
            const int bidx = ((ih - jh + 6)*13 + (iw - jw + 6));
            sval = acc * 13.856406460551018f + rel_bias[bidx*NHEAD + h];
        }
        sS[i*LW + j] = sval;
    }
    __syncthreads();

    if (tid < LW) {
        float mx = -1e30f;
        #pragma unroll
        for (int j = 0; j < LW; ++j) mx = fmaxf(mx, sS[tid*LW + j]);
        float sum = 0.f;
        #pragma unroll
        for (int j = 0; j < LW; ++j) {
            const float e = expf(sS[tid*LW + j] - mx);
            sS[tid*LW + j] = e;
            sum += e;
        }
        const float inv = 1.0f / sum;
        #pragma unroll
        for (int j = 0; j < LW; ++j) sS[tid*LW + j] *= inv;
    }
    __syncthreads();

    for (int t = tid; t < LW*HDIM; t += 128) {
        const int i = t >> 5, d = t & 31;
        float acc = 0.f;
        #pragma unroll
        for (int j = 0; j < LW; ++j)
            acc += sS[i*LW + j] * sV[j*32 + d];
        g_attn[(size_t)(w*LW + i)*CCH + h*HDIM + d] = acc;
    }
}

// ---------------- window-reverse + unroll + residual ----------------
__global__ void scatter_res_kernel(const float* __restrict__ x)
{
    const long total = (long)MTOK * CCH;
    for (long idx = (long)blockIdx.x*blockDim.x + threadIdx.x;
         idx < total; idx += (long)gridDim.x*blockDim.x) {
        const int m = (int)(idx / CCH);
        const int c = (int)(idx % CCH);
        const int b = m / LLEN, l = m % LLEN;
        const int h = l / IMGW, w = l % IMGW;
        int hp = h - SHIFT_; if (hp < 0) hp += IMGH;
        int wp = w - SHIFT_; if (wp < 0) wp += IMGW;
        const int widx  = b*NWIN + (hp/WSZ)*8 + (wp/WSZ);
        const int local = (hp%WSZ)*WSZ + (wp%WSZ);
        g_xres[idx] = x[idx] + g_proj[(size_t)(widx*LW + local)*CCH + c];
    }
}

// ---------------- launch ----------------
extern "C" void kernel_launch(void* const* d_in, const int* in_sizes, int n_in,
                              void* d_out, int out_size)
{
    const void* arr[20];
    int na = 0;
    for (int i = 0; i < n_in && na < 20; ++i)
        if (in_sizes[i] != 1) arr[na++] = d_in[i];
    const float* x     = (const float*)arr[0];
    const float* n1w   = (const float*)arr[3];
    const float* n1b   = (const float*)arr[4];
    const float* qkvw  = (const float*)arr[5];
    const float* relb  = (const float*)arr[6];
    const float* projw = (const float*)arr[7];
    const float* projb = (const float*)arr[8];
    const float* n2w   = (const float*)arr[9];
    const float* n2b   = (const float*)arr[10];
    const float* fc1w  = (const float*)arr[11];
    const float* fc1b  = (const float*)arr[12];
    const float* fc2w  = (const float*)arr[13];
    const float* fc2b  = (const float*)arr[14];
    float* out = (float*)d_out;

    float* p_xw;   cudaGetSymbolAddress((void**)&p_xw,   g_xw);
    float* p_qkv;  cudaGetSymbolAddress((void**)&p_qkv,  g_qkv);
    float* p_attn; cudaGetSymbolAddress((void**)&p_attn, g_attn);
    float* p_proj; cudaGetSymbolAddress((void**)&p_proj, g_proj);
    float* p_xres; cudaGetSymbolAddress((void**)&p_xres, g_xres);
    float* p_ln2;  cudaGetSymbolAddress((void**)&p_ln2,  g_ln2);
    float* p_h1;   cudaGetSymbolAddress((void**)&p_h1,   g_h1);

    // 1) LN1 + roll + window partition
    ln_kernel<true><<<MTOK, CCH>>>(x, n1w, n1b, p_xw);

    // 2) QKV GEMM
    gemm_tc<0, false, false><<<dim3(576/64, MTOK/128), 256>>>(
        p_xw, qkvw, nullptr, nullptr, p_qkv, MTOK, 3*CCH, CCH);

    // 3) fused windowed attention
    attn_kernel<<<dim3(NHEAD, NWTOT), 128>>>(relb);

    // 4) proj GEMM (+bias)
    gemm_tc<0, true, false><<<dim3(192/64, MTOK/128), 256>>>(
        p_attn, projw, projb, nullptr, p_proj, MTOK, CCH, CCH);

    // 5) window reverse + roll back + residual
    scatter_res_kernel<<<4096, 256>>>(x);

    // 6) LN2
    ln_kernel<false><<<MTOK, CCH>>>(p_xres, n2w, n2b, p_ln2);

    // 7) fc1 GEMM + bias + gelu
    gemm_tc<1, true, false><<<dim3(768/64, MTOK/128), 256>>>(
        p_ln2, fc1w, fc1b, nullptr, p_h1, MTOK, 4*CCH, CCH);

    // 8) fc2 GEMM + bias + gelu (faithful quirk) + residual -> d_out
    gemm_tc<1, true, true><<<dim3(192/64, MTOK/128), 256>>>(
        p_h1, fc2w, fc2b, p_xres, out, MTOK, CCH, 4*CCH);

    (void)out_size;
}

// round 4
// speedup vs baseline: 2.5364x; 1.1272x over previous
#include <cuda_runtime.h>
#include <cuda_bf16.h>
#include <math.h>
#include <stdint.h>

// ---------------- static problem shape ----------------
#define BATCH 32
#define IMGH  56
#define IMGW  56
#define CCH   192
#define LLEN  (IMGH*IMGW)        // 3136
#define NHEAD 6
#define HDIM  32
#define WSZ   7
#define SHIFT_ 3
#define LW    49
#define NWIN  64
#define NWTOT (BATCH*NWIN)       // 2048
#define MTOK  (BATCH*LLEN)       // 100352

// ---------------- scratch ----------------
__device__ float g_qkv  [(size_t)MTOK*3*CCH];
__device__ float g_attn [(size_t)MTOK*CCH];
__device__ float g_xres [(size_t)MTOK*CCH];
__device__ float g_h1   [(size_t)MTOK*4*CCH];
__device__ float g_st1  [(size_t)MTOK*2];      // mean,rstd of x
__device__ float g_st2  [(size_t)MTOK*2];      // mean,rstd of xres

__device__ __forceinline__ float gelu_exact(float x) {
    return 0.5f * x * (1.0f + erff(x * 0.70710678118654752f));
}
__device__ __forceinline__ uint32_t pack_bf16x2(float lo, float hi) {
    uint32_t o;
    asm("cvt.rn.bf16x2.f32 %0, %1, %2;" : "=r"(o) : "f"(hi), "f"(lo));
    return o;
}
__device__ __forceinline__ void mma_bf16(float c[4], const uint32_t a[4], const uint32_t b[2]) {
    asm volatile(
        "mma.sync.aligned.m16n8k16.row.col.f32.bf16.bf16.f32 "
        "{%0,%1,%2,%3}, {%4,%5,%6,%7}, {%8,%9}, {%0,%1,%2,%3};"
        : "+f"(c[0]), "+f"(c[1]), "+f"(c[2]), "+f"(c[3])
        : "r"(a[0]), "r"(a[1]), "r"(a[2]), "r"(a[3]), "r"(b[0]), "r"(b[1]));
}

// window-layout row -> original token index (inverse of roll+partition)
__device__ __forceinline__ int winrow_to_token(int wr) {
    const int w  = wr / LW, local = wr % LW;
    const int b  = w >> 6, wl = w & 63;
    const int hp = (wl >> 3)*WSZ + local/WSZ;
    const int wp = (wl & 7)*WSZ + local%WSZ;
    int h = hp + SHIFT_; if (h >= IMGH) h -= IMGH;
    int ww = wp + SHIFT_; if (ww >= IMGW) ww -= IMGW;
    return b*LLEN + h*IMGW + ww;
}

// ---------------- LN stats: one warp per token ----------------
__global__ void __launch_bounds__(256)
ln_stats_kernel(const float* __restrict__ in, float* __restrict__ stats)
{
    const int warp = (blockIdx.x * 256 + threadIdx.x) >> 5;
    const int lane = threadIdx.x & 31;
    if (warp >= MTOK) return;
    const float* p = in + (size_t)warp*CCH;
    float s = 0.f, s2 = 0.f;
    #pragma unroll
    for (int i = 0; i < 6; ++i) {
        const float v = p[lane + i*32];
        s += v; s2 += v*v;
    }
    #pragma unroll
    for (int off = 16; off > 0; off >>= 1) {
        s  += __shfl_down_sync(0xffffffff, s,  off);
        s2 += __shfl_down_sync(0xffffffff, s2, off);
    }
    if (lane == 0) {
        const float mean = s * (1.0f/CCH);
        const float var  = s2 * (1.0f/CCH) - mean*mean;
        stats[2*warp]   = mean;
        stats[2*warp+1] = rsqrtf(var + 1e-5f);
    }
}

// ---------------- BF16 TC GEMM with fused A-side LN / gather and fused epilogues ----
// AOP: 0=plain A, 1=LN(A) via stats, 2=LN(A)+window-gather rows
// ACT: 0=none, 1=gelu
// WOP: 0=plain write, 1=scatter rows to token layout + add residual (x)
#define RS 20
#define ABUF (128*RS)
#define BBUF (64*RS)
template<int AOP, int ACT, bool HAS_BIAS, bool HAS_RES, int WOP>
__global__ void __launch_bounds__(256)
gemm_tc(const float* __restrict__ A, const float* __restrict__ W,
        const float* __restrict__ bias, const float* __restrict__ res,
        const float* __restrict__ stats,
        const float* __restrict__ gamma, const float* __restrict__ beta,
        float* __restrict__ out, int M, int N, int K)
{
    const int tid  = threadIdx.x;
    const int lane = tid & 31;
    const int warp = tid >> 5;
    const int warpM = warp & 3;
    const int warpN = warp >> 2;
    const int m0 = blockIdx.y * 128;
    const int n0 = blockIdx.x * 64;

    __shared__ uint32_t sA[2*ABUF];
    __shared__ uint32_t sB[2*BBUF];

    float acc[2][4][4];
    #pragma unroll
    for (int i = 0; i < 2; ++i)
        #pragma unroll
        for (int j = 0; j < 4; ++j)
            #pragma unroll
            for (int q = 0; q < 4; ++q) acc[i][j][q] = 0.f;

    const int aK4 = (tid & 7) << 2;
    const int kw0 = (tid & 7) << 1;
    const int aR0 = tid >> 3;
    const int laneR = lane >> 2;
    const int laneK = lane & 3;
    uint32_t* baseA = &sA[(warpM*32 + laneR)*RS + laneK];
    uint32_t* baseB = &sB[(warpN*32 + laneR)*RS + laneK];

    // A row sources (+ LN row constants), resolved once
    int aSrc[4];
    float aMean[4], aRstd[4];
    #pragma unroll
    for (int r = 0; r < 4; ++r) {
        const int wr = m0 + aR0 + r*32;
        aSrc[r] = (AOP == 2) ? winrow_to_token(wr) : wr;
        if (AOP != 0) {
            aMean[r] = stats[2*aSrc[r]];
            aRstd[r] = stats[2*aSrc[r]+1];
        }
    }

    float4 ra[4], rb[2];
    #pragma unroll
    for (int r = 0; r < 4; ++r)
        ra[r] = *reinterpret_cast<const float4*>(&A[(size_t)aSrc[r]*K + aK4]);
    #pragma unroll
    for (int r = 0; r < 2; ++r)
        rb[r] = *reinterpret_cast<const float4*>(&W[(size_t)(n0 + aR0 + r*32)*K + aK4]);

    const int ntiles = K >> 5;
    // store helper captured as lambda-ish macro
    #define STORE_TILE(stage, koff)                                              \
    {                                                                            \
        float4 gm4, bt4;                                                         \
        if (AOP != 0) {                                                          \
            gm4 = *reinterpret_cast<const float4*>(&gamma[(koff) + aK4]);        \
            bt4 = *reinterpret_cast<const float4*>(&beta [(koff) + aK4]);        \
        }                                                                        \
        _Pragma("unroll")                                                        \
        for (int r = 0; r < 4; ++r) {                                            \
            float vx = ra[r].x, vy = ra[r].y, vz = ra[r].z, vw = ra[r].w;        \
            if (AOP != 0) {                                                      \
                vx = (vx - aMean[r])*aRstd[r]*gm4.x + bt4.x;                     \
                vy = (vy - aMean[r])*aRstd[r]*gm4.y + bt4.y;                     \
                vz = (vz - aMean[r])*aRstd[r]*gm4.z + bt4.z;                     \
                vw = (vw - aMean[r])*aRstd[r]*gm4.w + bt4.w;                     \
            }                                                                    \
            uint32_t* p = &sA[(stage)*ABUF + (aR0 + r*32)*RS + kw0];             \
            p[0] = pack_bf16x2(vx, vy);                                          \
            p[1] = pack_bf16x2(vz, vw);                                          \
        }                                                                        \
        _Pragma("unroll")                                                        \
        for (int r = 0; r < 2; ++r) {                                            \
            uint32_t* p = &sB[(stage)*BBUF + (aR0 + r*32)*RS + kw0];             \
            p[0] = pack_bf16x2(rb[r].x, rb[r].y);                                \
            p[1] = pack_bf16x2(rb[r].z, rb[r].w);                                \
        }                                                                        \
    }

    STORE_TILE(0, 0)

    for (int t = 0; t < ntiles; ++t) {
        __syncthreads();
        const bool more = (t + 1 < ntiles);
        if (more) {
            const int k0 = (t+1) << 5;
            #pragma unroll
            for (int r = 0; r < 4; ++r)
                ra[r] = *reinterpret_cast<const float4*>(&A[(size_t)aSrc[r]*K + k0 + aK4]);
            #pragma unroll
            for (int r = 0; r < 2; ++r)
                rb[r] = *reinterpret_cast<const float4*>(&W[(size_t)(n0 + aR0 + r*32)*K + k0 + aK4]);
        }

        const uint32_t* pA = baseA + (t & 1)*ABUF;
        const uint32_t* pB = baseB + (t & 1)*BBUF;
        #pragma unroll
        for (int ks = 0; ks < 2; ++ks) {
            uint32_t af[2][4], bf[4][2];
            #pragma unroll
            for (int mt = 0; mt < 2; ++mt) {
                const uint32_t* q = pA + mt*(16*RS) + ks*8;
                af[mt][0] = q[0];
                af[mt][1] = q[8*RS];
                af[mt][2] = q[4];
                af[mt][3] = q[8*RS + 4];
            }
            #pragma unroll
            for (int nt = 0; nt < 4; ++nt) {
                const uint32_t* q = pB + nt*(8*RS) + ks*8;
                bf[nt][0] = q[0];
                bf[nt][1] = q[4];
            }
            #pragma unroll
            for (int mt = 0; mt < 2; ++mt)
                #pragma unroll
                for (int nt = 0; nt < 4; ++nt)
                    mma_bf16(acc[mt][nt], af[mt], bf[nt]);
        }

        if (more) {
            const int st = (t + 1) & 1;
            const int k0u = (t+1) << 5;
            STORE_TILE(st, k0u)
        }
    }
    #undef STORE_TILE

    // epilogue
    #pragma unroll
    for (int mt = 0; mt < 2; ++mt) {
        #pragma unroll
        for (int nt = 0; nt < 4; ++nt) {
            const int col = n0 + warpN*32 + nt*8 + (laneK << 1);
            const float b0 = HAS_BIAS ? bias[col]   : 0.f;
            const float b1 = HAS_BIAS ? bias[col+1] : 0.f;
            #pragma unroll
            for (int half = 0; half < 2; ++half) {
                const int wr = m0 + warpM*32 + mt*16 + laneR + half*8;
                const int row = (WOP == 1) ? winrow_to_token(wr) : wr;
                float v0 = acc[mt][nt][half*2+0] + b0;
                float v1 = acc[mt][nt][half*2+1] + b1;
                if (ACT == 1) { v0 = gelu_exact(v0); v1 = gelu_exact(v1); }
                if (HAS_RES || WOP == 1) {
                    const float2 r2 = *reinterpret_cast<const float2*>(&res[(size_t)row*N + col]);
                    v0 += r2.x; v1 += r2.y;
                }
                *reinterpret_cast<float2*>(&out[(size_t)row*N + col]) = make_float2(v0, v1);
            }
        }
    }
}

// ---------------- fused attention per (window, head) ----------------
__device__ __forceinline__ int regid(int p) { return (p < 49) ? 0 : ((p < 53) ? 1 : 2); }

__global__ void __launch_bounds__(128)
attn_kernel(const float* __restrict__ rel_bias)
{
    const int h = blockIdx.x;
    const int w = blockIdx.y;
    const int tid = threadIdx.x;

    __shared__ float sQ[LW*33];
    __shared__ float sK[LW*33];
    __shared__ float sV[LW*32];
    __shared__ float sS[LW*LW];

    for (int t = tid; t < LW*HDIM; t += 128) {
        const int i = t >> 5, d = t & 31;
        const size_t base = (size_t)(w*LW + i) * (3*CCH);
        sQ[i*33 + d] = g_qkv[base + h*HDIM + d];
        sK[i*33 + d] = g_qkv[base + CCH + h*HDIM + d];
        sV[i*32 + d] = g_qkv[base + 2*CCH + h*HDIM + d];
    }
    __syncthreads();

    const int wl  = w & (NWIN-1);
    const int wh_ = wl >> 3, ww_ = wl & 7;
    for (int t = tid; t < LW*LW; t += 128) {
        const int i = t / LW, j = t % LW;
        const int ih = i / WSZ, iw = i % WSZ;
        const int jh = j / WSZ, jw = j % WSZ;
        const int idi = regid(wh_*WSZ + ih)*3 + regid(ww_*WSZ + iw);
        const int idj = regid(wh_*WSZ + jh)*3 + regid(ww_*WSZ + jw);
        float sval;
        if (idi != idj) {
            sval = -100.0f;
        } else {
            float acc = 0.f;
            #pragma unroll
            for (int d = 0; d < HDIM; ++d)
                acc += sQ[i*33 + d] * sK[j*33 + d];
            const int bidx = ((ih - jh + 6)*13 + (iw - jw + 6));
            sval = acc * 13.856406460551018f + rel_bias[bidx*NHEAD + h];
        }
        sS[i*LW + j] = sval;
    }
    __syncthreads();

    if (tid < LW) {
        float mx = -1e30f;
        #pragma unroll
        for (int j = 0; j < LW; ++j) mx = fmaxf(mx, sS[tid*LW + j]);
        float sum = 0.f;
        #pragma unroll
        for (int j = 0; j < LW; ++j) {
            const float e = expf(sS[tid*LW + j] - mx);
            sS[tid*LW + j] = e;
            sum += e;
        }
        const float inv = 1.0f / sum;
        #pragma unroll
        for (int j = 0; j < LW; ++j) sS[tid*LW + j] *= inv;
    }
    __syncthreads();

    for (int t = tid; t < LW*HDIM; t += 128) {
        const int i = t >> 5, d = t & 31;
        float acc = 0.f;
        #pragma unroll
        for (int j = 0; j < LW; ++j)
            acc += sS[i*LW + j] * sV[j*32 + d];
        g_attn[(size_t)(w*LW + i)*CCH + h*HDIM + d] = acc;
    }
}

// ---------------- launch ----------------
extern "C" void kernel_launch(void* const* d_in, const int* in_sizes, int n_in,
                              void* d_out, int out_size)
{
    const void* arr[20];
    int na = 0;
    for (int i = 0; i < n_in && na < 20; ++i)
        if (in_sizes[i] != 1) arr[na++] = d_in[i];
    const float* x     = (const float*)arr[0];
    const float* n1w   = (const float*)arr[3];
    const float* n1b   = (const float*)arr[4];
    const float* qkvw  = (const float*)arr[5];
    const float* relb  = (const float*)arr[6];
    const float* projw = (const float*)arr[7];
    const float* projb = (const float*)arr[8];
    const float* n2w   = (const float*)arr[9];
    const float* n2b   = (const float*)arr[10];
    const float* fc1w  = (const float*)arr[11];
    const float* fc1b  = (const float*)arr[12];
    const float* fc2w  = (const float*)arr[13];
    const float* fc2b  = (const float*)arr[14];
    float* out = (float*)d_out;

    float* p_qkv;  cudaGetSymbolAddress((void**)&p_qkv,  g_qkv);
    float* p_attn; cudaGetSymbolAddress((void**)&p_attn, g_attn);
    float* p_xres; cudaGetSymbolAddress((void**)&p_xres, g_xres);
    float* p_h1;   cudaGetSymbolAddress((void**)&p_h1,   g_h1);
    float* p_st1;  cudaGetSymbolAddress((void**)&p_st1,  g_st1);
    float* p_st2;  cudaGetSymbolAddress((void**)&p_st2,  g_st2);

    // 1) LN1 stats
    ln_stats_kernel<<<MTOK/8, 256>>>(x, p_st1);

    // 2) QKV GEMM with fused LN1 + roll/window gather
    gemm_tc<2, 0, false, false, 0><<<dim3(576/64, MTOK/128), 256>>>(
        x, qkvw, nullptr, nullptr, p_st1, n1w, n1b, p_qkv, MTOK, 3*CCH, CCH);

    // 3) fused windowed attention
    attn_kernel<<<dim3(NHEAD, NWTOT), 128>>>(relb);

    // 4) proj GEMM + bias + window-reverse scatter + residual(x) -> g_xres
    gemm_tc<0, 0, true, false, 1><<<dim3(192/64, MTOK/128), 256>>>(
        p_attn, projw, projb, x, nullptr, nullptr, nullptr, p_xres, MTOK, CCH, CCH);

    // 5) LN2 stats
    ln_stats_kernel<<<MTOK/8, 256>>>(p_xres, p_st2);

    // 6) fc1 GEMM with fused LN2, + bias + gelu
    gemm_tc<1, 1, true, false, 0><<<dim3(768/64, MTOK/128), 256>>>(
        p_xres, fc1w, fc1b, nullptr, p_st2, n2w, n2b, p_h1, MTOK, 4*CCH, CCH);

    // 7) fc2 GEMM + bias + gelu (faithful quirk) + residual -> d_out
    gemm_tc<0, 1, true, true, 0><<<dim3(192/64, MTOK/128), 256>>>(
        p_h1, fc2w, fc2b, p_xres, nullptr, nullptr, nullptr, out, MTOK, CCH, 4*CCH);

    (void)out_size;
}